// round 7
// baseline (speedup 1.0000x reference)
#include <cuda_runtime.h>
#include <cuda_fp16.h>
#include <cstdint>

// out[b,o] = sum_{i,j} (x_a^j x_b^(8-j))[b,i] * (coeffs[o,i,j]*weights[o,i])
// GEMM: M=16384, N=256, K=2304 (=16 chunks of 144). HMMA m16n8k16 path.
// R7: 512 threads / 16 warps (4 per SMSP), warp tile 32x64 -> 2x latency
//     hiding for ldsm->mma chains; same CTA tile, same smem staging.

#define BATCH   16384
#define IDIM    256
#define ODIM    256
#define CTAM    128
#define NCHUNK  16
#define PLANES  18
#define THREADS 512

#define A_PLANE 2064                        // 128 rows * 16B + 16B pad
#define A_STAGE (PLANES * A_PLANE)          // 37152
#define B_PLANE (ODIM * 16)                 // 4096
#define B_STAGE (PLANES * B_PLANE)          // 73728
#define SM_B    (2 * A_STAGE)               // 74304
#define SMEM_TOTAL (SM_B + 2 * B_STAGE)     // 221760

#define TWO_LOG2E 2.8853900817779268f

// Prefolded B operand: [chunk 16][plane 18][col 256][8 halves] = 1.18 MB
__device__ __align__(128) __half g_B[NCHUNK * PLANES * ODIM * 8];

__device__ __forceinline__ uint32_t s2u(const void* p) {
    return (uint32_t)__cvta_generic_to_shared(p);
}

// ---------------------------------------------------------------- prep kernel
__global__ void bern_prep(const float* __restrict__ weights,
                          const float* __restrict__ coeffs) {
    int gid = blockIdx.x * blockDim.x + threadIdx.x;   // 73728
    int o   = gid & 255;
    int idx = gid >> 8;
    int pl  = idx % PLANES;
    int c   = idx / PLANES;

    __half h[8];
    if (pl < 16) {
        int i = c * 16 + pl;
        float w = weights[o * IDIM + i];
        const float* cf = coeffs + (size_t)(o * IDIM + i) * 9;
#pragma unroll
        for (int j = 0; j < 8; j++) h[j] = __float2half_rn(cf[j] * w);
    } else {
#pragma unroll
        for (int off = 0; off < 8; off++) {
            int i = c * 16 + (pl - 16) * 8 + off;
            float w = weights[o * IDIM + i];
            h[off] = __float2half_rn(coeffs[((size_t)(o * IDIM + i)) * 9 + 8] * w);
        }
    }
    uint32_t u[4];
#pragma unroll
    for (int j = 0; j < 4; j++) {
        __half2 p = __halves2half2(h[2 * j], h[2 * j + 1]);
        u[j] = *reinterpret_cast<uint32_t*>(&p);
    }
    *reinterpret_cast<uint4*>(
        reinterpret_cast<char*>(g_B) + ((size_t)(c * PLANES + pl) * ODIM + o) * 16) =
        make_uint4(u[0], u[1], u[2], u[3]);
}

// ---------------------------------------------------------------- main kernel
__global__ void __launch_bounds__(THREADS, 1)
bern_gemm(const float* __restrict__ x, float* __restrict__ out) {
    extern __shared__ char smem[];
    const int tid  = threadIdx.x;
    const int wid  = tid >> 5;       // 0..15
    const int lane = tid & 31;
    const int mbase = blockIdx.x * CTAM;
    const int wm = wid & 3;          // 4 warps along M (32 rows each)
    const int wn = wid >> 2;         // 4 warps along N (64 cols each)

    float acc[2][8][4];
#pragma unroll
    for (int a = 0; a < 2; a++)
#pragma unroll
        for (int b = 0; b < 8; b++)
#pragma unroll
            for (int d = 0; d < 4; d++) acc[a][b][d] = 0.0f;

    const int prow = (lane >> 2);
    const int pii  = (lane & 3);

    // ---- issue the 4 x-loads for chunk c (results land later)
    auto load_x = [&](int c, float* xv) {
        const float* xp = x + (size_t)mbase * IDIM + c * 16;
#pragma unroll
        for (int q = 0; q < 4; q++) {
            int grp = wid * 4 + q;                   // 0..63
            int row = (grp & 15) * 8 + prow;
            int ii  = (grp >> 4) * 4 + pii;
            xv[q] = xp[row * IDIM + ii];
        }
    };

    // ---- produce A chunk into stage s from prefetched x values
    auto produce = [&](int s, const float* xv) {
        char* aS = smem + s * A_STAGE;
#pragma unroll
        for (int q = 0; q < 4; q++) {
            int grp = wid * 4 + q;
            int row = (grp & 15) * 8 + prow;
            int ii  = (grp >> 4) * 4 + pii;
            float e  = exp2f(xv[q] * TWO_LOG2E);
            float t  = 1.0f - __fdividef(2.0f, e + 1.0f);
            float a = 1.0f + t, b = 1.0f - t;
            float ab = a * b, ab2 = ab * ab, ab3 = ab2 * ab, ab4 = ab2 * ab2;
            float a2 = a * a, b2 = b * b;
            float a4 = a2 * a2, b4 = b2 * b2;
            float a6 = a4 * a2, b6 = b4 * b2;
            float a8 = a4 * a4, b8 = b4 * b4;
            uint32_t u0, u1, u2, u3;
            { __half2 p = __floats2half2_rn(b8,       ab * b6);  u0 = *reinterpret_cast<uint32_t*>(&p); }
            { __half2 p = __floats2half2_rn(ab2 * b4, ab3 * b2); u1 = *reinterpret_cast<uint32_t*>(&p); }
            { __half2 p = __floats2half2_rn(ab4,      ab3 * a2); u2 = *reinterpret_cast<uint32_t*>(&p); }
            { __half2 p = __floats2half2_rn(ab2 * a4, ab * a6);  u3 = *reinterpret_cast<uint32_t*>(&p); }
            *reinterpret_cast<uint4*>(aS + ii * A_PLANE + row * 16) =
                make_uint4(u0, u1, u2, u3);
            *reinterpret_cast<__half*>(aS + (16 + (ii >> 3)) * A_PLANE + row * 16 +
                                       (ii & 7) * 2) = __float2half_rn(a8);
        }
    };

    auto loadB = [&](int c, int s) {
        const char* src = reinterpret_cast<const char*>(g_B) + (size_t)c * B_STAGE;
        char* dst = smem + SM_B + s * B_STAGE;
#pragma unroll
        for (int r = 0; r < B_STAGE / 16 / THREADS; r++) {   // 9
            int idx = (r * THREADS + tid) * 16;
            asm volatile("cp.async.cg.shared.global [%0], [%1], 16;"
                         :: "r"(s2u(dst + idx)), "l"(src + idx) : "memory");
        }
        asm volatile("cp.async.commit_group;" ::: "memory");
    };

    // ---- mma over slices [kk0, kk1) of stage s; warp tile 32x64
    auto domma = [&](int s, int kk0, int kk1) {
        char* aS = smem + s * A_STAGE;
        char* bS = smem + SM_B + s * B_STAGE;
        const int arow = wm * 32 + (lane & 7) + ((lane >> 3) & 1) * 8;
        const int apl  = (lane >> 4);
        const int bcol = wn * 64 + (lane & 7) + ((lane >> 4) & 1) * 8;
        const int bpl  = (lane >> 3) & 1;
#pragma unroll
        for (int kk = kk0; kk < kk1; kk++) {
            uint32_t afr[2][4];
#pragma unroll
            for (int mt = 0; mt < 2; mt++) {
                uint32_t ad = s2u(aS + (kk * 2 + apl) * A_PLANE + (arow + mt * 16) * 16);
                asm volatile("ldmatrix.sync.aligned.m8n8.x4.shared.b16 {%0,%1,%2,%3}, [%4];"
                             : "=r"(afr[mt][0]), "=r"(afr[mt][1]),
                               "=r"(afr[mt][2]), "=r"(afr[mt][3]) : "r"(ad));
            }
            uint32_t bfr[4][4];
#pragma unroll
            for (int g = 0; g < 4; g++) {
                uint32_t bd = s2u(bS + (kk * 2 + bpl) * B_PLANE + (bcol + g * 16) * 16);
                asm volatile("ldmatrix.sync.aligned.m8n8.x4.shared.b16 {%0,%1,%2,%3}, [%4];"
                             : "=r"(bfr[g][0]), "=r"(bfr[g][1]),
                               "=r"(bfr[g][2]), "=r"(bfr[g][3]) : "r"(bd));
            }
#pragma unroll
            for (int mt = 0; mt < 2; mt++)
#pragma unroll
                for (int g = 0; g < 4; g++)
#pragma unroll
                    for (int sub = 0; sub < 2; sub++) {
                        float* d = acc[mt][g * 2 + sub];
                        asm volatile(
                            "mma.sync.aligned.m16n8k16.row.col.f32.f16.f16.f32 "
                            "{%0,%1,%2,%3}, {%4,%5,%6,%7}, {%8,%9}, {%0,%1,%2,%3};"
                            : "+f"(d[0]), "+f"(d[1]), "+f"(d[2]), "+f"(d[3])
                            : "r"(afr[mt][0]), "r"(afr[mt][1]),
                              "r"(afr[mt][2]), "r"(afr[mt][3]),
                              "r"(bfr[g][sub * 2]), "r"(bfr[g][sub * 2 + 1]));
                    }
        }
    };

    // ---- pipeline
    float xv[4], xn[4];
    load_x(0, xv);
    loadB(0, 0);
    produce(0, xv);
    __syncthreads();
    for (int c = 0; c < NCHUNK; c++) {
        int s = c & 1;
        if (c + 1 < NCHUNK) {
            load_x(c + 1, xn);                       // LDGs in flight
            loadB(c + 1, s ^ 1);
            asm volatile("cp.async.wait_group 1;" ::: "memory");
            domma(s, 0, 5);                          // covers the x LDG latency
            produce(s ^ 1, xn);
            domma(s, 5, 9);
        } else {
            asm volatile("cp.async.wait_group 0;" ::: "memory");
            domma(s, 0, 9);
        }
        __syncthreads();
    }

    // ---- epilogue
#pragma unroll
    for (int mt = 0; mt < 2; mt++) {
        int row0 = mbase + wm * 32 + mt * 16 + (lane >> 2);
#pragma unroll
        for (int nf = 0; nf < 8; nf++) {
            int col = wn * 64 + nf * 8 + (lane & 3) * 2;
            *reinterpret_cast<float2*>(out + (size_t)row0 * ODIM + col) =
                make_float2(acc[mt][nf][0], acc[mt][nf][1]);
            *reinterpret_cast<float2*>(out + (size_t)(row0 + 8) * ODIM + col) =
                make_float2(acc[mt][nf][2], acc[mt][nf][3]);
        }
    }
}

// ---------------------------------------------------------------- launch
extern "C" void kernel_launch(void* const* d_in, const int* in_sizes, int n_in,
                              void* d_out, int out_size) {
    const float* x       = (const float*)d_in[0];  // [16384, 256]
    const float* weights = (const float*)d_in[1];  // [256, 256]
    const float* coeffs  = (const float*)d_in[2];  // [256, 256, 9]
    float* out = (float*)d_out;                    // [16384, 256] fp32

    cudaFuncSetAttribute(bern_gemm, cudaFuncAttributeMaxDynamicSharedMemorySize,
                         SMEM_TOTAL);

    bern_prep<<<(NCHUNK * PLANES * ODIM) / 256, 256>>>(weights, coeffs);
    bern_gemm<<<BATCH / CTAM, THREADS, SMEM_TOTAL>>>(x, out);
}

// round 8
// speedup vs baseline: 1.0867x; 1.0867x over previous
#include <cuda_runtime.h>
#include <cuda_fp16.h>
#include <cstdint>

// out[b,o] = sum_{i,j} (x_a^j x_b^(8-j))[b,i] * (coeffs[o,i,j]*weights[o,i])
// GEMM: M=16384, N=256, K=2304 (=16 chunks of 144). HMMA m16n8k16 path.
// R8: (1) register double-buffered ldmatrix fragments (slice kk+1 preloaded
//     under slice kk's HMMAs); (2) coalesced prep kernel (block=o, tid=i).
//     256 threads, warp tile 64x64.

#define BATCH   16384
#define IDIM    256
#define ODIM    256
#define CTAM    128
#define NCHUNK  16
#define PLANES  18
#define THREADS 256

#define A_PLANE 2064                        // 128 rows * 16B + 16B pad
#define A_STAGE (PLANES * A_PLANE)          // 37152
#define B_PLANE (ODIM * 16)                 // 4096
#define B_STAGE (PLANES * B_PLANE)          // 73728
#define SM_B    (2 * A_STAGE)               // 74304
#define SMEM_TOTAL (SM_B + 2 * B_STAGE)     // 221760

#define TWO_LOG2E 2.8853900817779268f

// Prefolded B operand: [chunk 16][plane 18][col 256][8 halves] = 1.18 MB
__device__ __align__(128) __half g_B[NCHUNK * PLANES * ODIM * 8];

__device__ __forceinline__ uint32_t s2u(const void* p) {
    return (uint32_t)__cvta_generic_to_shared(p);
}

// ---------------------------------------------------------------- prep kernel
// block = o (256 blocks), tid = i (256 threads): weights/coeffs reads coalesced.
__global__ void bern_prep(const float* __restrict__ weights,
                          const float* __restrict__ coeffs) {
    int o = blockIdx.x;
    int i = threadIdx.x;

    float w = weights[o * IDIM + i];
    const float* cf = coeffs + (size_t)(o * IDIM + i) * 9;
    float c[9];
#pragma unroll
    for (int j = 0; j < 9; j++) c[j] = cf[j] * w;

    int cc = i >> 4;          // chunk
    int pl = i & 15;          // plane within chunk (j=0..7 block)

    uint32_t u[4];
#pragma unroll
    for (int j = 0; j < 4; j++) {
        __half2 p = __floats2half2_rn(c[2 * j], c[2 * j + 1]);
        u[j] = *reinterpret_cast<uint32_t*>(&p);
    }
    char* base = reinterpret_cast<char*>(g_B);
    *reinterpret_cast<uint4*>(base + ((size_t)(cc * PLANES + pl) * ODIM + o) * 16) =
        make_uint4(u[0], u[1], u[2], u[3]);
    // j = 8 straggler: plane 16 + (ii>>3), half slot ii&7
    int spl = 16 + ((i >> 3) & 1);
    *reinterpret_cast<__half*>(base + ((size_t)(cc * PLANES + spl) * ODIM + o) * 16 +
                               (i & 7) * 2) = __float2half_rn(c[8]);
}

// ---------------------------------------------------------------- main kernel
__global__ void __launch_bounds__(THREADS, 1)
bern_gemm(const float* __restrict__ x, float* __restrict__ out) {
    extern __shared__ char smem[];
    const int tid  = threadIdx.x;
    const int wid  = tid >> 5;
    const int lane = tid & 31;
    const int mbase = blockIdx.x * CTAM;
    const int wm = wid & 1;        // 2 warps along M (64 rows each)
    const int wn = wid >> 1;       // 4 warps along N (64 cols each)

    float acc[4][8][4];
#pragma unroll
    for (int a = 0; a < 4; a++)
#pragma unroll
        for (int b = 0; b < 8; b++)
#pragma unroll
            for (int d = 0; d < 4; d++) acc[a][b][d] = 0.0f;

    const int prow = (lane >> 2);
    const int pii  = (lane & 3);

    auto load_x = [&](int c, float* xv) {
        const float* xp = x + (size_t)mbase * IDIM + c * 16;
#pragma unroll
        for (int q = 0; q < 8; q++) {
            int grp = wid * 8 + q;
            int row = (grp & 15) * 8 + prow;
            int ii  = (grp >> 4) * 4 + pii;
            xv[q] = xp[row * IDIM + ii];
        }
    };

    auto produce = [&](int s, const float* xv) {
        char* aS = smem + s * A_STAGE;
#pragma unroll
        for (int q = 0; q < 8; q++) {
            int grp = wid * 8 + q;
            int row = (grp & 15) * 8 + prow;
            int ii  = (grp >> 4) * 4 + pii;
            float e  = exp2f(xv[q] * TWO_LOG2E);
            float t  = 1.0f - __fdividef(2.0f, e + 1.0f);
            float a = 1.0f + t, b = 1.0f - t;
            float ab = a * b, ab2 = ab * ab, ab3 = ab2 * ab, ab4 = ab2 * ab2;
            float a2 = a * a, b2 = b * b;
            float a4 = a2 * a2, b4 = b2 * b2;
            float a6 = a4 * a2, b6 = b4 * b2;
            float a8 = a4 * a4, b8 = b4 * b4;
            uint32_t u0, u1, u2, u3;
            { __half2 p = __floats2half2_rn(b8,       ab * b6);  u0 = *reinterpret_cast<uint32_t*>(&p); }
            { __half2 p = __floats2half2_rn(ab2 * b4, ab3 * b2); u1 = *reinterpret_cast<uint32_t*>(&p); }
            { __half2 p = __floats2half2_rn(ab4,      ab3 * a2); u2 = *reinterpret_cast<uint32_t*>(&p); }
            { __half2 p = __floats2half2_rn(ab2 * a4, ab * a6);  u3 = *reinterpret_cast<uint32_t*>(&p); }
            *reinterpret_cast<uint4*>(aS + ii * A_PLANE + row * 16) =
                make_uint4(u0, u1, u2, u3);
            *reinterpret_cast<__half*>(aS + (16 + (ii >> 3)) * A_PLANE + row * 16 +
                                       (ii & 7) * 2) = __float2half_rn(a8);
        }
    };

    auto loadB = [&](int c, int s) {
        const char* src = reinterpret_cast<const char*>(g_B) + (size_t)c * B_STAGE;
        char* dst = smem + SM_B + s * B_STAGE;
#pragma unroll
        for (int r = 0; r < B_STAGE / 16 / THREADS; r++) {   // 18
            int idx = (r * THREADS + tid) * 16;
            asm volatile("cp.async.cg.shared.global [%0], [%1], 16;"
                         :: "r"(s2u(dst + idx)), "l"(src + idx) : "memory");
        }
        asm volatile("cp.async.commit_group;" ::: "memory");
    };

    const int arow = wm * 64 + (lane & 7) + ((lane >> 3) & 1) * 8;
    const int apl  = (lane >> 4);
    const int bcol = wn * 64 + (lane & 7) + ((lane >> 4) & 1) * 8;
    const int bpl  = (lane >> 3) & 1;

    // load all fragments of slice kk into af/bf
    auto loadfrag = [&](char* aS, char* bS, int kk,
                        uint32_t (*af)[4], uint32_t (*bf)[4]) {
#pragma unroll
        for (int mt = 0; mt < 4; mt++) {
            uint32_t ad = s2u(aS + (kk * 2 + apl) * A_PLANE + (arow + mt * 16) * 16);
            asm volatile("ldmatrix.sync.aligned.m8n8.x4.shared.b16 {%0,%1,%2,%3}, [%4];"
                         : "=r"(af[mt][0]), "=r"(af[mt][1]),
                           "=r"(af[mt][2]), "=r"(af[mt][3]) : "r"(ad));
        }
#pragma unroll
        for (int g = 0; g < 4; g++) {
            uint32_t bd = s2u(bS + (kk * 2 + bpl) * B_PLANE + (bcol + g * 16) * 16);
            asm volatile("ldmatrix.sync.aligned.m8n8.x4.shared.b16 {%0,%1,%2,%3}, [%4];"
                         : "=r"(bf[g][0]), "=r"(bf[g][1]),
                           "=r"(bf[g][2]), "=r"(bf[g][3]) : "r"(bd));
        }
    };

    auto hmma_slice = [&](uint32_t (*af)[4], uint32_t (*bf)[4]) {
#pragma unroll
        for (int mt = 0; mt < 4; mt++)
#pragma unroll
            for (int g = 0; g < 4; g++)
#pragma unroll
                for (int sub = 0; sub < 2; sub++) {
                    float* d = acc[mt][g * 2 + sub];
                    asm volatile(
                        "mma.sync.aligned.m16n8k16.row.col.f32.f16.f16.f32 "
                        "{%0,%1,%2,%3}, {%4,%5,%6,%7}, {%8,%9}, {%0,%1,%2,%3};"
                        : "+f"(d[0]), "+f"(d[1]), "+f"(d[2]), "+f"(d[3])
                        : "r"(af[mt][0]), "r"(af[mt][1]),
                          "r"(af[mt][2]), "r"(af[mt][3]),
                          "r"(bf[g][sub * 2]), "r"(bf[g][sub * 2 + 1]));
                }
    };

    // mma over slices [kk0, kk1) with register double-buffered fragments
    auto domma = [&](int s, int kk0, int kk1) {
        char* aS = smem + s * A_STAGE;
        char* bS = smem + SM_B + s * B_STAGE;
        uint32_t afr[2][4][4], bfr[2][4][4];
        loadfrag(aS, bS, kk0, afr[0], bfr[0]);
#pragma unroll
        for (int kk = kk0; kk < kk1; kk++) {
            int cur = (kk - kk0) & 1;
            if (kk + 1 < kk1)
                loadfrag(aS, bS, kk + 1, afr[cur ^ 1], bfr[cur ^ 1]);
            hmma_slice(afr[cur], bfr[cur]);
        }
    };

    // ---- pipeline
    float xv[8], xn[8];
    load_x(0, xv);
    loadB(0, 0);
    produce(0, xv);
    __syncthreads();
    for (int c = 0; c < NCHUNK; c++) {
        int s = c & 1;
        if (c + 1 < NCHUNK) {
            load_x(c + 1, xn);                       // x LDGs in flight
            loadB(c + 1, s ^ 1);
            asm volatile("cp.async.wait_group 1;" ::: "memory");
            domma(s, 0, 5);                          // covers x LDG latency
            produce(s ^ 1, xn);
            domma(s, 5, 9);
        } else {
            asm volatile("cp.async.wait_group 0;" ::: "memory");
            domma(s, 0, 9);
        }
        __syncthreads();
    }

    // ---- epilogue
#pragma unroll
    for (int mt = 0; mt < 4; mt++) {
        int row0 = mbase + wm * 64 + mt * 16 + (lane >> 2);
#pragma unroll
        for (int nf = 0; nf < 8; nf++) {
            int col = wn * 64 + nf * 8 + (lane & 3) * 2;
            *reinterpret_cast<float2*>(out + (size_t)row0 * ODIM + col) =
                make_float2(acc[mt][nf][0], acc[mt][nf][1]);
            *reinterpret_cast<float2*>(out + (size_t)(row0 + 8) * ODIM + col) =
                make_float2(acc[mt][nf][2], acc[mt][nf][3]);
        }
    }
}

// ---------------------------------------------------------------- launch
extern "C" void kernel_launch(void* const* d_in, const int* in_sizes, int n_in,
                              void* d_out, int out_size) {
    const float* x       = (const float*)d_in[0];  // [16384, 256]
    const float* weights = (const float*)d_in[1];  // [256, 256]
    const float* coeffs  = (const float*)d_in[2];  // [256, 256, 9]
    float* out = (float*)d_out;                    // [16384, 256] fp32

    cudaFuncSetAttribute(bern_gemm, cudaFuncAttributeMaxDynamicSharedMemorySize,
                         SMEM_TOTAL);

    bern_prep<<<ODIM, IDIM>>>(weights, coeffs);
    bern_gemm<<<BATCH / CTAM, THREADS, SMEM_TOTAL>>>(x, out);
}

// round 9
// speedup vs baseline: 1.2406x; 1.1417x over previous
#include <cuda_runtime.h>
#include <cuda_fp16.h>
#include <cstdint>

// out[b,o] = sum_i f_{o,i}(tanh(x[b,i])),  f = order-8 Bernstein polynomial.
// R9: re-express f in Chebyshev basis of t=tanh(x):
//        f(t) = q0 + sum_{j=1..8} q_j T_j(t)
//     q0 folds into a per-o bias => GEMM K drops 2304 -> 2048 (-11% HMMA),
//     no straggler planes, produce = one STS.128 per task.
// GEMM: M=16384, N=256, K=2048 (16 chunks of 128 = 8 k16 slices each).

#define BATCH   16384
#define IDIM    256
#define ODIM    256
#define CTAM    128
#define NCHUNK  16
#define PLANES  16
#define THREADS 256

#define A_PLANE 2064                        // 128 rows * 16B + 16B pad
#define A_STAGE (PLANES * A_PLANE)          // 33024
#define B_PLANE (ODIM * 16)                 // 4096
#define B_STAGE (PLANES * B_PLANE)          // 65536
#define SM_B    (2 * A_STAGE)               // 66048
#define SMEM_TOTAL (SM_B + 2 * B_STAGE)     // 197120

#define TWO_LOG2E 2.8853900817779268f

// Chebyshev-basis B operand: [chunk 16][plane 16][col 256][8 halves] = 1 MB
__device__ __align__(128) __half g_B[NCHUNK * PLANES * ODIM * 8];
__device__ float g_bias[ODIM];

__device__ __forceinline__ uint32_t s2u(const void* p) {
    return (uint32_t)__cvta_generic_to_shared(p);
}

// ---------------------------------------------------------------- prep kernel
// block = o, tid = i. c_k = coeffs*w -> power basis -> Chebyshev basis (fp32).
__global__ void bern_prep(const float* __restrict__ weights,
                          const float* __restrict__ coeffs) {
    // Bernstein (1+t)^k (1-t)^(8-k) -> power t^n
    static const float M[9][9] = {
        { 1, -8,  28, -56,  70, -56,  28, -8,  1},
        { 1, -6,  14, -14,   0,  14, -14,  6, -1},
        { 1, -4,   4,   4, -10,   4,   4, -4,  1},
        { 1, -2,  -2,   6,   0,  -6,   2,  2, -1},
        { 1,  0,  -4,   0,   6,   0,  -4,  0,  1},
        { 1,  2,  -2,  -6,   0,   6,   2, -2, -1},
        { 1,  4,   4,  -4, -10,  -4,   4,  4,  1},
        { 1,  6,  14,  14,   0, -14, -14, -6, -1},
        { 1,  8,  28,  56,  70,  56,  28,  8,  1}
    };
    int o = blockIdx.x;
    int i = threadIdx.x;

    float w = weights[o * IDIM + i];
    const float* cf = coeffs + (size_t)(o * IDIM + i) * 9;
    float c[9];
#pragma unroll
    for (int k = 0; k < 9; k++) c[k] = cf[k] * w;

    float p[9];
#pragma unroll
    for (int n = 0; n < 9; n++) {
        float s = 0.0f;
#pragma unroll
        for (int k = 0; k < 9; k++) s += c[k] * M[k][n];
        p[n] = s;
    }
    // power -> Chebyshev
    float q0 = p[0] + 0.5f * p[2] + 0.375f * p[4] + 0.3125f * p[6] + 0.2734375f * p[8];
    float q1 = p[1] + 0.75f * p[3] + 0.625f * p[5] + 0.546875f * p[7];
    float q2 = 0.5f * p[2] + 0.5f * p[4] + 0.46875f * p[6] + 0.4375f * p[8];
    float q3 = 0.25f * p[3] + 0.3125f * p[5] + 0.328125f * p[7];
    float q4 = 0.125f * p[4] + 0.1875f * p[6] + 0.21875f * p[8];
    float q5 = 0.0625f * p[5] + 0.109375f * p[7];
    float q6 = 0.03125f * p[6] + 0.0625f * p[8];
    float q7 = 0.015625f * p[7];
    float q8 = 0.0078125f * p[8];

    uint32_t u[4];
    { __half2 h = __floats2half2_rn(q1, q2); u[0] = *reinterpret_cast<uint32_t*>(&h); }
    { __half2 h = __floats2half2_rn(q3, q4); u[1] = *reinterpret_cast<uint32_t*>(&h); }
    { __half2 h = __floats2half2_rn(q5, q6); u[2] = *reinterpret_cast<uint32_t*>(&h); }
    { __half2 h = __floats2half2_rn(q7, q8); u[3] = *reinterpret_cast<uint32_t*>(&h); }
    int cc = i >> 4, pl = i & 15;
    *reinterpret_cast<uint4*>(reinterpret_cast<char*>(g_B) +
        ((size_t)(cc * PLANES + pl) * ODIM + o) * 16) = make_uint4(u[0], u[1], u[2], u[3]);

    // deterministic block reduction of q0 -> bias[o]
    __shared__ float red[IDIM];
    red[i] = q0;
    __syncthreads();
#pragma unroll
    for (int st = IDIM / 2; st > 0; st >>= 1) {
        if (i < st) red[i] += red[i + st];
        __syncthreads();
    }
    if (i == 0) g_bias[o] = red[0];
}

// ---------------------------------------------------------------- main kernel
__global__ void __launch_bounds__(THREADS, 1)
bern_gemm(const float* __restrict__ x, float* __restrict__ out) {
    extern __shared__ char smem[];
    const int tid  = threadIdx.x;
    const int wid  = tid >> 5;
    const int lane = tid & 31;
    const int mbase = blockIdx.x * CTAM;
    const int wm = wid & 1;        // 2 warps along M (64 rows each)
    const int wn = wid >> 1;       // 4 warps along N (64 cols each)

    float acc[4][8][4];
#pragma unroll
    for (int a = 0; a < 4; a++)
#pragma unroll
        for (int b = 0; b < 8; b++)
#pragma unroll
            for (int d = 0; d < 4; d++) acc[a][b][d] = 0.0f;

    const int prow = (lane >> 2);
    const int pii  = (lane & 3);

    auto load_x = [&](int c, float* xv) {
        const float* xp = x + (size_t)mbase * IDIM + c * 16;
#pragma unroll
        for (int q = 0; q < 8; q++) {
            int grp = wid * 8 + q;
            int row = (grp & 15) * 8 + prow;
            int ii  = (grp >> 4) * 4 + pii;
            xv[q] = xp[row * IDIM + ii];
        }
    };

    // A[row, i-plane] = {T_1(t) .. T_8(t)} as 8 fp16 (one STS.128)
    auto produce = [&](int s, const float* xv) {
        char* aS = smem + s * A_STAGE;
#pragma unroll
        for (int q = 0; q < 8; q++) {
            int grp = wid * 8 + q;
            int row = (grp & 15) * 8 + prow;
            int ii  = (grp >> 4) * 4 + pii;
            float e  = exp2f(xv[q] * TWO_LOG2E);
            float t  = 1.0f - __fdividef(2.0f, e + 1.0f);
            float t2 = t + t;
            float T1 = t;
            float T2 = __fmaf_rn(t2, T1, -1.0f);
            float T3 = __fmaf_rn(t2, T2, -T1);
            float T4 = __fmaf_rn(t2, T3, -T2);
            float T5 = __fmaf_rn(t2, T4, -T3);
            float T6 = __fmaf_rn(t2, T5, -T4);
            float T7 = __fmaf_rn(t2, T6, -T5);
            float T8 = __fmaf_rn(t2, T7, -T6);
            uint32_t u0, u1, u2, u3;
            { __half2 p = __floats2half2_rn(T1, T2); u0 = *reinterpret_cast<uint32_t*>(&p); }
            { __half2 p = __floats2half2_rn(T3, T4); u1 = *reinterpret_cast<uint32_t*>(&p); }
            { __half2 p = __floats2half2_rn(T5, T6); u2 = *reinterpret_cast<uint32_t*>(&p); }
            { __half2 p = __floats2half2_rn(T7, T8); u3 = *reinterpret_cast<uint32_t*>(&p); }
            *reinterpret_cast<uint4*>(aS + ii * A_PLANE + row * 16) =
                make_uint4(u0, u1, u2, u3);
        }
    };

    auto loadB = [&](int c, int s) {
        const char* src = reinterpret_cast<const char*>(g_B) + (size_t)c * B_STAGE;
        char* dst = smem + SM_B + s * B_STAGE;
#pragma unroll
        for (int r = 0; r < B_STAGE / 16 / THREADS; r++) {   // 16
            int idx = (r * THREADS + tid) * 16;
            asm volatile("cp.async.cg.shared.global [%0], [%1], 16;"
                         :: "r"(s2u(dst + idx)), "l"(src + idx) : "memory");
        }
        asm volatile("cp.async.commit_group;" ::: "memory");
    };

    const int arow = wm * 64 + (lane & 7) + ((lane >> 3) & 1) * 8;
    const int apl  = (lane >> 4);
    const int bcol = wn * 64 + (lane & 7) + ((lane >> 4) & 1) * 8;
    const int bpl  = (lane >> 3) & 1;

    auto loadfrag = [&](char* aS, char* bS, int kk,
                        uint32_t (*af)[4], uint32_t (*bf)[4]) {
#pragma unroll
        for (int mt = 0; mt < 4; mt++) {
            uint32_t ad = s2u(aS + (kk * 2 + apl) * A_PLANE + (arow + mt * 16) * 16);
            asm volatile("ldmatrix.sync.aligned.m8n8.x4.shared.b16 {%0,%1,%2,%3}, [%4];"
                         : "=r"(af[mt][0]), "=r"(af[mt][1]),
                           "=r"(af[mt][2]), "=r"(af[mt][3]) : "r"(ad));
        }
#pragma unroll
        for (int g = 0; g < 4; g++) {
            uint32_t bd = s2u(bS + (kk * 2 + bpl) * B_PLANE + (bcol + g * 16) * 16);
            asm volatile("ldmatrix.sync.aligned.m8n8.x4.shared.b16 {%0,%1,%2,%3}, [%4];"
                         : "=r"(bf[g][0]), "=r"(bf[g][1]),
                           "=r"(bf[g][2]), "=r"(bf[g][3]) : "r"(bd));
        }
    };

    auto hmma_slice = [&](uint32_t (*af)[4], uint32_t (*bf)[4]) {
#pragma unroll
        for (int mt = 0; mt < 4; mt++)
#pragma unroll
            for (int g = 0; g < 4; g++)
#pragma unroll
                for (int sub = 0; sub < 2; sub++) {
                    float* d = acc[mt][g * 2 + sub];
                    asm volatile(
                        "mma.sync.aligned.m16n8k16.row.col.f32.f16.f16.f32 "
                        "{%0,%1,%2,%3}, {%4,%5,%6,%7}, {%8,%9}, {%0,%1,%2,%3};"
                        : "+f"(d[0]), "+f"(d[1]), "+f"(d[2]), "+f"(d[3])
                        : "r"(af[mt][0]), "r"(af[mt][1]),
                          "r"(af[mt][2]), "r"(af[mt][3]),
                        "r"(bf[g][sub * 2]), "r"(bf[g][sub * 2 + 1]));
                }
    };

    auto domma = [&](int s, int kk0, int kk1) {
        char* aS = smem + s * A_STAGE;
        char* bS = smem + SM_B + s * B_STAGE;
        uint32_t afr[2][4][4], bfr[2][4][4];
        loadfrag(aS, bS, kk0, afr[0], bfr[0]);
#pragma unroll
        for (int kk = kk0; kk < kk1; kk++) {
            int cur = (kk - kk0) & 1;
            if (kk + 1 < kk1)
                loadfrag(aS, bS, kk + 1, afr[cur ^ 1], bfr[cur ^ 1]);
            hmma_slice(afr[cur], bfr[cur]);
        }
    };

    // ---- pipeline
    float xv[8], xn[8];
    load_x(0, xv);
    loadB(0, 0);
    produce(0, xv);
    __syncthreads();
    for (int c = 0; c < NCHUNK; c++) {
        int s = c & 1;
        if (c + 1 < NCHUNK) {
            load_x(c + 1, xn);                       // x LDGs in flight
            loadB(c + 1, s ^ 1);
            asm volatile("cp.async.wait_group 1;" ::: "memory");
            domma(s, 0, 4);                          // covers x LDG latency
            produce(s ^ 1, xn);
            domma(s, 4, 8);
        } else {
            asm volatile("cp.async.wait_group 0;" ::: "memory");
            domma(s, 0, 8);
        }
        __syncthreads();
    }

    // ---- epilogue (+ per-o bias from the T0 terms)
#pragma unroll
    for (int mt = 0; mt < 4; mt++) {
        int row0 = mbase + wm * 64 + mt * 16 + (lane >> 2);
#pragma unroll
        for (int nf = 0; nf < 8; nf++) {
            int col = wn * 64 + nf * 8 + (lane & 3) * 2;
            float2 bv = *reinterpret_cast<const float2*>(g_bias + col);
            *reinterpret_cast<float2*>(out + (size_t)row0 * ODIM + col) =
                make_float2(acc[mt][nf][0] + bv.x, acc[mt][nf][1] + bv.y);
            *reinterpret_cast<float2*>(out + (size_t)(row0 + 8) * ODIM + col) =
                make_float2(acc[mt][nf][2] + bv.x, acc[mt][nf][3] + bv.y);
        }
    }
}

// ---------------------------------------------------------------- launch
extern "C" void kernel_launch(void* const* d_in, const int* in_sizes, int n_in,
                              void* d_out, int out_size) {
    const float* x       = (const float*)d_in[0];  // [16384, 256]
    const float* weights = (const float*)d_in[1];  // [256, 256]
    const float* coeffs  = (const float*)d_in[2];  // [256, 256, 9]
    float* out = (float*)d_out;                    // [16384, 256] fp32

    cudaFuncSetAttribute(bern_gemm, cudaFuncAttributeMaxDynamicSharedMemorySize,
                         SMEM_TOTAL);

    bern_prep<<<ODIM, IDIM>>>(weights, coeffs);
    bern_gemm<<<BATCH / CTAM, THREADS, SMEM_TOTAL>>>(x, out);
}